// round 10
// baseline (speedup 1.0000x reference)
#include <cuda_runtime.h>

// Shapes (fixed by the problem)
#define Bn   8
#define NIN  4096
#define DIN  128
#define KOUT 256

#define ADJ_F4_PER_B (NIN * NIN / 4)    // 4,194,304 float4 per batch (64 MB)

#define ADJ_BLOCKS  1024
#define NODE_BLOCKS 128                 // 16 per batch
#define NPB         (NODE_BLOCKS / Bn)  // 16
#define RTHREADS    256
#define GT          (ADJ_BLOCKS * RTHREADS)   // 262,144 f4 grid stride (4 MB)
#define F4_PER_THREAD 16                // per batch: 16 * GT = ADJ_F4_PER_B  ✓
#define WPB         (ADJ_BLOCKS * 8)    // 8192 warp partials per batch

// Scratch — every slot fully overwritten each launch (deterministic, no init).
__device__ float g_part[Bn * WPB];          // per-batch, per-WARP adj partials
__device__ float g_node_part[NODE_BLOCKS * DIN];

// ---------------------------------------------------------------------------
// Kernel 1: the 531 MB pass — TLB-friendly sweep, ZERO block barriers.
//   blocks [0, 1024):    for each batch b: grid-stride sweep of that batch's
//                        64 MB; each WARP writes its own partial (no
//                        __syncthreads anywhere -> next batch's loads issue
//                        while this batch's shuffle/store drains).
//   blocks [1024, 1152): partial colsum of node_set, then exit.
// C == ones exactly (reference softmax is over a size-1 axis), so these
// reductions are the entire data-dependent work of the layer.
// ---------------------------------------------------------------------------
__global__ void __launch_bounds__(RTHREADS, 8)
mp_reduce_kernel(const float* __restrict__ adj,
                 const float* __restrict__ node,
                 const float* __restrict__ lin_w) {
    const int bid = blockIdx.x;
    const int t   = threadIdx.x;

    if (bid < ADJ_BLOCKS) {
        const int w    = t >> 5;
        const int lane = t & 31;
        const int gtid = bid * RTHREADS + t;

        #pragma unroll 1
        for (int b = 0; b < Bn; b++) {
            const float4* __restrict__ base =
                reinterpret_cast<const float4*>(adj) + (size_t)b * ADJ_F4_PER_B + gtid;

            // 16 grid-strided float4 loads, 4 independent accumulators.
            float a0 = 0.f, a1 = 0.f, a2 = 0.f, a3 = 0.f;
            #pragma unroll
            for (int i = 0; i < F4_PER_THREAD / 4; i++) {
                float4 v0 = __ldcs(base + (size_t)(4 * i + 0) * GT);
                float4 v1 = __ldcs(base + (size_t)(4 * i + 1) * GT);
                float4 v2 = __ldcs(base + (size_t)(4 * i + 2) * GT);
                float4 v3 = __ldcs(base + (size_t)(4 * i + 3) * GT);
                a0 += (v0.x + v0.y) + (v0.z + v0.w);
                a1 += (v1.x + v1.y) + (v1.z + v1.w);
                a2 += (v2.x + v2.y) + (v2.z + v2.w);
                a3 += (v3.x + v3.y) + (v3.z + v3.w);
            }
            float v = (a0 + a1) + (a2 + a3);

            // warp tree (fixed order) -> lane 0 stores the warp partial
            #pragma unroll
            for (int off = 16; off > 0; off >>= 1)
                v += __shfl_xor_sync(0xffffffffu, v, off);
            if (lane == 0)
                g_part[b * WPB + bid * 8 + w] = v;
            // no barrier: batch b+1 loads overlap this store
        }
    } else {
        // ---- node partial colsum: 256 n-rows per block ----
        __shared__ __align__(16) float sf[DIN];
        const int nb   = bid - ADJ_BLOCKS;                        // 0..127
        const int b    = nb / NPB;
        const int sub  = nb % NPB;
        const int rows = NIN / NPB;                               // 256
        const float* __restrict__ base = node + ((size_t)b * NIN + sub * rows) * DIN;

        const int d      = t & (DIN - 1);
        const int stripe = t >> 7;                                // 0 or 1

        float acc = 0.0f;
        #pragma unroll 4
        for (int r = stripe * 128; r < stripe * 128 + 128; r++)
            acc += base[(size_t)r * DIN + d];

        if (stripe == 0) sf[d] = acc;
        __syncthreads();
        if (stripe == 1) g_node_part[nb * DIN + d] = acc + sf[d];

        // Warm lin_w into L2 for the tail kernel's GEMVs.
        float w = lin_w[nb * DIN + d];
        asm volatile("" :: "f"(w));
    }
}

// ---------------------------------------------------------------------------
// Kernel 2 (tail, PDL): 96 blocks per batch; minimal-barrier critical path.
//   s in [0,32):  node fill — colsum + GEMV from L2-hot partials,
//                 write 256 float4 of new_node_set[b].
//   s in [32,96): adj fill — reduce the 8192 L2-hot warp partials (fixed
//                 order), write 256 float4 of new_adj[b].
// Every block of a batch computes in the identical FP order -> deterministic.
// ---------------------------------------------------------------------------
__global__ void __launch_bounds__(RTHREADS)
mp_tail_kernel(const float* __restrict__ lin_w,
               const float* __restrict__ lin_b,
               float* __restrict__ out) {
#if __CUDA_ARCH__ >= 900
    cudaGridDependencySynchronize();   // PDL: wait for mp_reduce_kernel
#endif
    const int b = blockIdx.x / 96;
    const int s = blockIdx.x % 96;
    const int t = threadIdx.x;

    if (s < 32) {
        // ---- node region ----
        __shared__ __align__(16) float c[DIN];
        __shared__ __align__(16) float r[DIN];

        if (t < DIN) {
            float acc = 0.0f;
            #pragma unroll
            for (int p = 0; p < NPB; p++)
                acc += g_node_part[(b * NPB + p) * DIN + t];
            c[t] = acc;
        }
        __syncthreads();

        if (t < DIN) {
            float a0 = 0.f, a1 = 0.f, a2 = 0.f, a3 = 0.f;
            #pragma unroll
            for (int q = 0; q < 32; q++) {
                a0 = fmaf(c[q],      lin_w[(q)      * DIN + t], a0);
                a1 = fmaf(c[q + 32], lin_w[(q + 32) * DIN + t], a1);
                a2 = fmaf(c[q + 64], lin_w[(q + 64) * DIN + t], a2);
                a3 = fmaf(c[q + 96], lin_w[(q + 96) * DIN + t], a3);
            }
            float v = ((a0 + a1) + (a2 + a3)) + lin_b[t];
            r[t] = (v >= 0.0f) ? v : 0.01f * v;
        }
        __syncthreads();

        float4* __restrict__ node_out =
            reinterpret_cast<float4*>(out) + (size_t)b * (KOUT * DIN / 4);
        const float4* __restrict__ r4 = reinterpret_cast<const float4*>(r);
        const int idx = s * RTHREADS + t;              // 0..8191
        node_out[idx] = r4[idx & (DIN / 4 - 1)];
    } else {
        // ---- adj region: reduce 8192 warp partials (fixed order) ----
        __shared__ float ws[8];

        const float* __restrict__ p = g_part + b * WPB;
        float a0 = 0.f, a1 = 0.f, a2 = 0.f, a3 = 0.f;
        #pragma unroll
        for (int k = 0; k < 32; k += 4) {
            a0 += p[t + (k + 0) * 256];
            a1 += p[t + (k + 1) * 256];
            a2 += p[t + (k + 2) * 256];
            a3 += p[t + (k + 3) * 256];
        }
        float v = (a0 + a1) + (a2 + a3);
        #pragma unroll
        for (int off = 16; off > 0; off >>= 1)
            v += __shfl_xor_sync(0xffffffffu, v, off);
        if ((t & 31) == 0) ws[t >> 5] = v;
        __syncthreads();
        const float a = ((ws[0] + ws[1]) + (ws[2] + ws[3]))
                      + ((ws[4] + ws[5]) + (ws[6] + ws[7]));

        float4* __restrict__ adj_out =
            reinterpret_cast<float4*>(out + (size_t)Bn * KOUT * DIN) +
            (size_t)b * (KOUT * KOUT / 4);
        adj_out[(s - 32) * RTHREADS + t] = make_float4(a, a, a, a);
    }
}

// ---------------------------------------------------------------------------
// Launch. Inputs (metadata order): node_set, adj, centroids, conv_w, conv_b,
// lin_w, lin_b. centroids/conv_* are mathematically dead (softmax over a
// size-1 axis makes C identically 1), so they are never read.
// ---------------------------------------------------------------------------
extern "C" void kernel_launch(void* const* d_in, const int* in_sizes, int n_in,
                              void* d_out, int out_size) {
    const float* node  = (const float*)d_in[0];
    const float* adj   = (const float*)d_in[1];
    const float* lin_w = (const float*)d_in[5];
    const float* lin_b = (const float*)d_in[6];
    float* out = (float*)d_out;

    mp_reduce_kernel<<<ADJ_BLOCKS + NODE_BLOCKS, RTHREADS>>>(adj, node, lin_w);

    // Tail with programmatic dependent launch (overlaps launch with reduce drain).
    cudaLaunchConfig_t cfg = {};
    cfg.gridDim  = dim3(Bn * 96);
    cfg.blockDim = dim3(RTHREADS);
    cfg.dynamicSmemBytes = 0;
    cfg.stream = 0;
    cudaLaunchAttribute attr[1];
    attr[0].id = cudaLaunchAttributeProgrammaticStreamSerialization;
    attr[0].val.programmaticStreamSerializationAllowed = 1;
    cfg.attrs = attr;
    cfg.numAttrs = 1;
    cudaLaunchKernelEx(&cfg, mp_tail_kernel, lin_w, lin_b, out);
}

// round 11
// speedup vs baseline: 1.0443x; 1.0443x over previous
#include <cuda_runtime.h>

// Shapes (fixed by the problem)
#define Bn   8
#define NIN  4096
#define DIN  128
#define KOUT 256

#define ADJ_F4_PER_B (NIN * NIN / 4)    // 4,194,304 float4 per batch (64 MB)

#define ADJ_BLOCKS  1024
#define NODE_BLOCKS 128                 // 16 per batch
#define NPB         (NODE_BLOCKS / Bn)  // 16
#define RTHREADS    256
#define GT          (ADJ_BLOCKS * RTHREADS)   // 262,144 f4 grid stride (4 MB)
#define F4_PER_THREAD 16                // per batch: 16 * GT = ADJ_F4_PER_B  ✓
#define CPB         ADJ_BLOCKS          // 1024 partials per batch

// Scratch — every slot fully overwritten each launch (deterministic, no init).
__device__ float g_part[Bn * CPB];          // per-batch, per-block adj partials
__device__ float g_node_part[NODE_BLOCKS * DIN];

// ---------------------------------------------------------------------------
// Kernel 1: the 531 MB pass — TLB/row-locality-friendly lockstep sweep.
//   blocks [0, 1024):    for each batch b: the WHOLE grid sweeps that batch's
//                        64 MB in lockstep (grid-stride). The per-batch
//                        __syncthreads is load-bearing: it keeps all warps'
//                        instantaneous footprint inside one narrow window
//                        (R10 removed it and regressed 82.4 -> 86.1).
//   blocks [1024, 1152): partial colsum of node_set, then exit.
// C == ones exactly (reference softmax is over a size-1 axis), so these
// reductions are the entire data-dependent work of the layer.
// ---------------------------------------------------------------------------
__global__ void __launch_bounds__(RTHREADS, 8)
mp_reduce_kernel(const float* __restrict__ adj,
                 const float* __restrict__ node,
                 const float* __restrict__ lin_w) {
    const int bid = blockIdx.x;
    const int t   = threadIdx.x;

    if (bid < ADJ_BLOCKS) {
        __shared__ float ws[16];                       // 2 banks x 8 warp sums
        const int gtid = bid * RTHREADS + t;

        #pragma unroll 1
        for (int b = 0; b < Bn; b++) {
            const float4* __restrict__ base =
                reinterpret_cast<const float4*>(adj) + (size_t)b * ADJ_F4_PER_B + gtid;

            // 16 grid-strided float4 loads, 4 independent accumulators.
            float a0 = 0.f, a1 = 0.f, a2 = 0.f, a3 = 0.f;
            #pragma unroll
            for (int i = 0; i < F4_PER_THREAD / 4; i++) {
                float4 v0 = __ldcs(base + (size_t)(4 * i + 0) * GT);
                float4 v1 = __ldcs(base + (size_t)(4 * i + 1) * GT);
                float4 v2 = __ldcs(base + (size_t)(4 * i + 2) * GT);
                float4 v3 = __ldcs(base + (size_t)(4 * i + 3) * GT);
                a0 += (v0.x + v0.y) + (v0.z + v0.w);
                a1 += (v1.x + v1.y) + (v1.z + v1.w);
                a2 += (v2.x + v2.y) + (v2.z + v2.w);
                a3 += (v3.x + v3.y) + (v3.z + v3.w);
            }
            float v = (a0 + a1) + (a2 + a3);

            // warp tree (fixed order) -> 8 warp sums -> t0 combines
            #pragma unroll
            for (int off = 16; off > 0; off >>= 1)
                v += __shfl_xor_sync(0xffffffffu, v, off);
            const int bank = (b & 1) * 8;
            if ((t & 31) == 0) ws[bank + (t >> 5)] = v;
            __syncthreads();
            if (t == 0) {
                const float* w8 = &ws[bank];
                g_part[b * CPB + bid] = ((w8[0] + w8[1]) + (w8[2] + w8[3]))
                                      + ((w8[4] + w8[5]) + (w8[6] + w8[7]));
            }
            // next batch uses the other bank; t0's read of this bank is done
            // before the next barrier publishes the other bank -> no hazard
        }
    } else {
        // ---- node partial colsum: 256 n-rows per block ----
        __shared__ __align__(16) float sf[DIN];
        const int nb   = bid - ADJ_BLOCKS;                        // 0..127
        const int b    = nb / NPB;
        const int sub  = nb % NPB;
        const int rows = NIN / NPB;                               // 256
        const float* __restrict__ base = node + ((size_t)b * NIN + sub * rows) * DIN;

        const int d      = t & (DIN - 1);
        const int stripe = t >> 7;                                // 0 or 1

        float acc = 0.0f;
        #pragma unroll 4
        for (int r = stripe * 128; r < stripe * 128 + 128; r++)
            acc += base[(size_t)r * DIN + d];

        if (stripe == 0) sf[d] = acc;
        __syncthreads();
        if (stripe == 1) g_node_part[nb * DIN + d] = acc + sf[d];

        // Warm lin_w into L2 for the tail kernel's GEMVs.
        float w = lin_w[nb * DIN + d];
        asm volatile("" :: "f"(w));
    }
}

// ---------------------------------------------------------------------------
// Kernel 2 (tail, PDL): 96 blocks per batch; minimal-barrier critical path.
//   s in [0,32):  node fill — colsum + GEMV from L2-hot partials,
//                 write 256 float4 of new_node_set[b].
//   s in [32,96): adj fill — reduce the 1024 L2-hot partials (fixed order),
//                 write 256 float4 of new_adj[b].
// Every block of a batch computes in the identical FP order -> deterministic.
// ---------------------------------------------------------------------------
__global__ void __launch_bounds__(RTHREADS)
mp_tail_kernel(const float* __restrict__ lin_w,
               const float* __restrict__ lin_b,
               float* __restrict__ out) {
#if __CUDA_ARCH__ >= 900
    cudaGridDependencySynchronize();   // PDL: wait for mp_reduce_kernel
#endif
    const int b = blockIdx.x / 96;
    const int s = blockIdx.x % 96;
    const int t = threadIdx.x;

    if (s < 32) {
        // ---- node region ----
        __shared__ __align__(16) float c[DIN];
        __shared__ __align__(16) float r[DIN];

        if (t < DIN) {
            float acc = 0.0f;
            #pragma unroll
            for (int p = 0; p < NPB; p++)
                acc += g_node_part[(b * NPB + p) * DIN + t];
            c[t] = acc;
        }
        __syncthreads();

        if (t < DIN) {
            float a0 = 0.f, a1 = 0.f, a2 = 0.f, a3 = 0.f;
            #pragma unroll
            for (int q = 0; q < 32; q++) {
                a0 = fmaf(c[q],      lin_w[(q)      * DIN + t], a0);
                a1 = fmaf(c[q + 32], lin_w[(q + 32) * DIN + t], a1);
                a2 = fmaf(c[q + 64], lin_w[(q + 64) * DIN + t], a2);
                a3 = fmaf(c[q + 96], lin_w[(q + 96) * DIN + t], a3);
            }
            float v = ((a0 + a1) + (a2 + a3)) + lin_b[t];
            r[t] = (v >= 0.0f) ? v : 0.01f * v;
        }
        __syncthreads();

        float4* __restrict__ node_out =
            reinterpret_cast<float4*>(out) + (size_t)b * (KOUT * DIN / 4);
        const float4* __restrict__ r4 = reinterpret_cast<const float4*>(r);
        const int idx = s * RTHREADS + t;              // 0..8191
        node_out[idx] = r4[idx & (DIN / 4 - 1)];
    } else {
        // ---- adj region: reduce 1024 partials (fixed order) ----
        __shared__ float ws[8];

        const float* __restrict__ p = g_part + b * CPB;
        float v = (p[t] + p[t + 256]) + (p[t + 512] + p[t + 768]);
        #pragma unroll
        for (int off = 16; off > 0; off >>= 1)
            v += __shfl_xor_sync(0xffffffffu, v, off);
        if ((t & 31) == 0) ws[t >> 5] = v;
        __syncthreads();
        const float a = ((ws[0] + ws[1]) + (ws[2] + ws[3]))
                      + ((ws[4] + ws[5]) + (ws[6] + ws[7]));

        float4* __restrict__ adj_out =
            reinterpret_cast<float4*>(out + (size_t)Bn * KOUT * DIN) +
            (size_t)b * (KOUT * KOUT / 4);
        adj_out[(s - 32) * RTHREADS + t] = make_float4(a, a, a, a);
    }
}

// ---------------------------------------------------------------------------
// Launch. Inputs (metadata order): node_set, adj, centroids, conv_w, conv_b,
// lin_w, lin_b. centroids/conv_* are mathematically dead (softmax over a
// size-1 axis makes C identically 1), so they are never read.
// ---------------------------------------------------------------------------
extern "C" void kernel_launch(void* const* d_in, const int* in_sizes, int n_in,
                              void* d_out, int out_size) {
    const float* node  = (const float*)d_in[0];
    const float* adj   = (const float*)d_in[1];
    const float* lin_w = (const float*)d_in[5];
    const float* lin_b = (const float*)d_in[6];
    float* out = (float*)d_out;

    mp_reduce_kernel<<<ADJ_BLOCKS + NODE_BLOCKS, RTHREADS>>>(adj, node, lin_w);

    // Tail with programmatic dependent launch (overlaps launch with reduce drain).
    cudaLaunchConfig_t cfg = {};
    cfg.gridDim  = dim3(Bn * 96);
    cfg.blockDim = dim3(RTHREADS);
    cfg.dynamicSmemBytes = 0;
    cfg.stream = 0;
    cudaLaunchAttribute attr[1];
    attr[0].id = cudaLaunchAttributeProgrammaticStreamSerialization;
    attr[0].val.programmaticStreamSerializationAllowed = 1;
    cfg.attrs = attr;
    cfg.numAttrs = 1;
    cudaLaunchKernelEx(&cfg, mp_tail_kernel, lin_w, lin_b, out);
}